// round 1
// baseline (speedup 1.0000x reference)
#include <cuda_runtime.h>
#include <math.h>

// ---------------- problem constants (compile-time) ----------------
#define N_P 100000
#define N_D 1000
#define N_S 5000
#define NT  (N_P + N_D + N_S)          // 106000
#define CD  64
#define HD  4
#define DHD 16
#define E0 300000
#define E1 300000
#define E2 100000
#define E3 100000
#define ET (E0 + E1 + E2 + E3)         // 800000
#define KREL_TOT (2*N_P + 2*N_D)       // 202000  (per-relation src-node tables)
#define DSTN_TOT (N_D + N_P + 2*N_S)   // 111000  (per-relation dst-node tables)

// ---------------- device scratch (no allocations allowed) ----------------
__device__ __align__(16) float g_x[NT * CD];          // current node features (concat P|D|S)
__device__ __align__(16) float g_q[NT * CD];          // Q per node
__device__ __align__(16) float g_krel[KREL_TOT * CD]; // relation-transformed K (per relation src set)
__device__ __align__(16) float g_vrel[KREL_TOT * CD]; // relation-transformed V
__device__ __align__(16) float g_alpha[ET * HD];      // per-edge per-head logits
__device__ __align__(16) float g_mx[DSTN_TOT * HD];   // segment max
__device__ __align__(16) float g_den[DSTN_TOT * HD];  // segment sum of exp
__device__ __align__(16) float g_num[DSTN_TOT * CD];  // unnormalized numerator
__device__ __align__(16) float g_Wc[16 * CD * CD];    // combined weights [l][kv][r] (l*8+kv*4+r)
__device__ __align__(16) float g_bc[16 * CD];         // combined biases

// ---------------- helpers ----------------
__device__ __forceinline__ void atomicMaxF(float* addr, float v) {
    // sign-split trick: works for mixed-sign floats, init must be -inf
    if (v >= 0.0f) atomicMax((int*)addr, __float_as_int(v));
    else           atomicMin((unsigned int*)addr, __float_as_uint(v));
}

// ---------------- combine weights:  Wc = W @ blockdiag(rel) * scale ----------------
// blk = l*8 + kv*4 + r ; kv=0: K-side (a_rel, scaled by p_rel*0.25), kv=1: V-side (m_rel)
__global__ void combine_weights(const float* __restrict__ Wk, const float* __restrict__ bk,
                                const float* __restrict__ Wv, const float* __restrict__ bv,
                                const float* __restrict__ a_rel, const float* __restrict__ m_rel,
                                const float* __restrict__ p_rel)
{
    int blk = blockIdx.x;
    int l  = blk >> 3;
    int kv = (blk >> 2) & 1;
    int r  = blk & 3;
    const int st_tab[4] = {0, 1, 1, 0};
    int st = st_tab[r];

    const float* Wbase = (kv == 0 ? Wk : Wv) + (size_t)(l*3 + st) * CD * CD;
    const float* bbase = (kv == 0 ? bk : bv) + (size_t)(l*3 + st) * CD;
    const float* rel   = (kv == 0 ? a_rel : m_rel) + (size_t)(l*4 + r) * HD * DHD * DHD;

    __shared__ float srel[HD * DHD * DHD]; // [h][d][e]
    __shared__ float sscale[HD];
    int t = threadIdx.x; // 256
    for (int i = t; i < HD*DHD*DHD; i += 256) srel[i] = rel[i];
    if (t < HD) sscale[t] = (kv == 0) ? p_rel[(l*4 + r) * HD + t] * 0.25f : 1.0f;
    __syncthreads();

    float* Wc = g_Wc + (size_t)blk * CD * CD;
    float* bc = g_bc + (size_t)blk * CD;

    int c = t >> 2;       // 0..63 input channel
    int h = t & 3;        // head
    float wrow[DHD];
#pragma unroll
    for (int d = 0; d < DHD; d++) wrow[d] = Wbase[c*CD + h*DHD + d];
    float sc = sscale[h];
#pragma unroll
    for (int e = 0; e < DHD; e++) {
        float s = 0.f;
#pragma unroll
        for (int d = 0; d < DHD; d++) s += wrow[d] * srel[h*256 + d*16 + e];
        Wc[c*CD + h*DHD + e] = s * sc;
    }
    if (t < CD) {
        int hh = t >> 4, ee = t & 15;
        float s = 0.f;
#pragma unroll
        for (int d = 0; d < DHD; d++) s += bbase[hh*DHD + d] * srel[hh*256 + d*16 + ee];
        bc[t] = s * sscale[hh];
    }
}

// ---------------- generic 64-wide GEMM:  Y[M,64] = op(X)[M,K] @ W[K,64] + b ----------------
// MODE 0: plain (X from memory)
// MODE 1: X = gelu( num0/den0 (+ num1/den1) ), epilogue: Y = s*(acc+b) + (1-s)*xold
template<int KDIM, int MODE>
__global__ void __launch_bounds__(128)
gemm64(const float* __restrict__ X, const float* __restrict__ W,
       const float* __restrict__ bias, float* __restrict__ Y, int M,
       const float* __restrict__ num0, const float* __restrict__ den0,
       const float* __restrict__ num1, const float* __restrict__ den1,
       const float* __restrict__ xold, const float* __restrict__ skipp)
{
    __shared__ float Xs[128 * 17];
    __shared__ float Ws[16 * 64];
    const int t  = threadIdx.x;
    const int m0 = blockIdx.x * 128;
    const int ty = t >> 3;   // 0..15 (row group)
    const int tx = t & 7;    // 0..7  (8 cols each)

    float acc[8][8];
#pragma unroll
    for (int i = 0; i < 8; i++)
#pragma unroll
        for (int j = 0; j < 8; j++) acc[i][j] = 0.f;

    for (int k0 = 0; k0 < KDIM; k0 += 16) {
        if (MODE == 0) {
#pragma unroll
            for (int i = 0; i < 4; i++) {
                int f4  = t + i * 128;          // 0..511
                int row = f4 >> 2, c4 = f4 & 3;
                float4 v = make_float4(0.f, 0.f, 0.f, 0.f);
                if (m0 + row < M)
                    v = *(const float4*)&X[(size_t)(m0 + row) * KDIM + k0 + c4 * 4];
                float* d = &Xs[row * 17 + c4 * 4];
                d[0] = v.x; d[1] = v.y; d[2] = v.z; d[3] = v.w;
            }
        } else {
#pragma unroll
            for (int i = 0; i < 16; i++) {
                int idx = t + i * 128;          // 0..2047
                int row = idx >> 4, cc = idx & 15;
                float val = 0.f;
                int n = m0 + row;
                if (n < M) {
                    int c = k0 + cc;
                    int h = c >> 4;
                    val = num0[(size_t)n * 64 + c] / (den0[(size_t)n * 4 + h] + 1e-16f);
                    if (num1)
                        val += num1[(size_t)n * 64 + c] / (den1[(size_t)n * 4 + h] + 1e-16f);
                    val = 0.5f * val * (1.0f + erff(val * 0.70710678118654752f)); // exact gelu
                }
                Xs[row * 17 + cc] = val;
            }
        }
#pragma unroll
        for (int i = 0; i < 2; i++) {
            int f4 = t + i * 128;               // 0..255
            int wr = f4 >> 4, c4 = f4 & 15;
            *(float4*)&Ws[wr * 64 + c4 * 4] = *(const float4*)&W[(size_t)(k0 + wr) * 64 + c4 * 4];
        }
        __syncthreads();
#pragma unroll
        for (int kk = 0; kk < 16; kk++) {
            float4 w0 = *(const float4*)&Ws[kk * 64 + tx * 8];
            float4 w1 = *(const float4*)&Ws[kk * 64 + tx * 8 + 4];
#pragma unroll
            for (int i = 0; i < 8; i++) {
                float xv = Xs[(ty + i * 16) * 17 + kk];
                acc[i][0] += xv * w0.x; acc[i][1] += xv * w0.y;
                acc[i][2] += xv * w0.z; acc[i][3] += xv * w0.w;
                acc[i][4] += xv * w1.x; acc[i][5] += xv * w1.y;
                acc[i][6] += xv * w1.z; acc[i][7] += xv * w1.w;
            }
        }
        __syncthreads();
    }

    float4 b0 = *(const float4*)&bias[tx * 8];
    float4 b1 = *(const float4*)&bias[tx * 8 + 4];
    float s = 0.f;
    if (MODE == 1) s = 1.0f / (1.0f + expf(-skipp[0]));

#pragma unroll
    for (int i = 0; i < 8; i++) {
        int row = m0 + ty + i * 16;
        if (row < M) {
            float o0 = acc[i][0] + b0.x, o1 = acc[i][1] + b0.y;
            float o2 = acc[i][2] + b0.z, o3 = acc[i][3] + b0.w;
            float o4 = acc[i][4] + b1.x, o5 = acc[i][5] + b1.y;
            float o6 = acc[i][6] + b1.z, o7 = acc[i][7] + b1.w;
            if (MODE == 1) {
                float4 x0 = *(const float4*)&xold[(size_t)row * 64 + tx * 8];
                float4 x1 = *(const float4*)&xold[(size_t)row * 64 + tx * 8 + 4];
                float om = 1.0f - s;
                o0 = s * o0 + om * x0.x; o1 = s * o1 + om * x0.y;
                o2 = s * o2 + om * x0.z; o3 = s * o3 + om * x0.w;
                o4 = s * o4 + om * x1.x; o5 = s * o5 + om * x1.y;
                o6 = s * o6 + om * x1.z; o7 = s * o7 + om * x1.w;
            }
            *(float4*)&Y[(size_t)row * 64 + tx * 8]     = make_float4(o0, o1, o2, o3);
            *(float4*)&Y[(size_t)row * 64 + tx * 8 + 4] = make_float4(o4, o5, o6, o7);
        }
    }
}

// ---------------- edge-relation decode ----------------
struct RelInfo { const int* ei; int er; int E; int kreloff; int qoff; int dnoff; };

__device__ __forceinline__ RelInfo decode_rel(int e, const int* ei0, const int* ei1,
                                              const int* ei2, const int* ei3)
{
    RelInfo ri;
    if (e < E0)                { ri.ei = ei0; ri.er = e;             ri.E = E0; ri.kreloff = 0;            ri.qoff = N_P;       ri.dnoff = 0; }
    else if (e < E0 + E1)      { ri.ei = ei1; ri.er = e - E0;        ri.E = E1; ri.kreloff = N_P;          ri.qoff = 0;         ri.dnoff = N_D; }
    else if (e < E0 + E1 + E2) { ri.ei = ei2; ri.er = e - (E0 + E1); ri.E = E2; ri.kreloff = N_P + N_D;    ri.qoff = N_P + N_D; ri.dnoff = N_D + N_P; }
    else                       { ri.ei = ei3; ri.er = e - (E0+E1+E2);ri.E = E3; ri.kreloff = N_P + 2*N_D;  ri.qoff = N_P + N_D; ri.dnoff = N_D + N_P + N_S; }
    return ri;
}

// ---------------- edge pass 1: logits + segment max ----------------
__global__ void edge_pass1(const int* __restrict__ ei0, const int* __restrict__ ei1,
                           const int* __restrict__ ei2, const int* __restrict__ ei3)
{
    int gid = blockIdx.x * blockDim.x + threadIdx.x;
    if (gid >= ET * HD) return;
    int e = gid >> 2, h = gid & 3;
    RelInfo ri = decode_rel(e, ei0, ei1, ei2, ei3);
    int src = ri.ei[ri.er];
    int dst = ri.ei[ri.E + ri.er];

    const float4* qp = (const float4*)&g_q[(size_t)(ri.qoff + dst) * 64 + h * 16];
    const float4* kp = (const float4*)&g_krel[(size_t)(ri.kreloff + src) * 64 + h * 16];
    float a = 0.f;
#pragma unroll
    for (int j = 0; j < 4; j++) {
        float4 q4 = qp[j], k4 = kp[j];
        a += q4.x * k4.x + q4.y * k4.y + q4.z * k4.z + q4.w * k4.w;
    }
    g_alpha[gid] = a;
    atomicMaxF(&g_mx[(size_t)(ri.dnoff + dst) * 4 + h], a);
}

// ---------------- edge pass 2: exp, denominator, numerator scatter ----------------
__global__ void edge_pass2(const int* __restrict__ ei0, const int* __restrict__ ei1,
                           const int* __restrict__ ei2, const int* __restrict__ ei3)
{
    int gid = blockIdx.x * blockDim.x + threadIdx.x;
    if (gid >= ET * HD) return;
    int e = gid >> 2, h = gid & 3;
    RelInfo ri = decode_rel(e, ei0, ei1, ei2, ei3);
    int src = ri.ei[ri.er];
    int dst = ri.ei[ri.E + ri.er];

    float a  = g_alpha[gid];
    float mx = g_mx[(size_t)(ri.dnoff + dst) * 4 + h];
    float w  = expf(a - mx);
    atomicAdd(&g_den[(size_t)(ri.dnoff + dst) * 4 + h], w);

    const float4* vp = (const float4*)&g_vrel[(size_t)(ri.kreloff + src) * 64 + h * 16];
    float4* np = (float4*)&g_num[(size_t)(ri.dnoff + dst) * 64 + h * 16];
#pragma unroll
    for (int j = 0; j < 4; j++) {
        float4 v4 = vp[j];
        atomicAdd(&np[j], make_float4(v4.x * w, v4.y * w, v4.z * w, v4.w * w)); // sm_90+ vector RED
    }
}

// ---------------- per-layer buffer init ----------------
__global__ void init_buffers()
{
    int i = blockIdx.x * blockDim.x + threadIdx.x;
    if (i < DSTN_TOT * HD) { g_mx[i] = __int_as_float(0xff800000); g_den[i] = 0.f; }
    if (i < DSTN_TOT * CD) g_num[i] = 0.f;
}

// ---------------- host orchestration ----------------
static inline int cdiv(int a, int b) { return (a + b - 1) / b; }

extern "C" void kernel_launch(void* const* d_in, const int* in_sizes, int n_in,
                              void* d_out, int out_size)
{
    const float* x_p   = (const float*)d_in[0];
    const float* x_d   = (const float*)d_in[1];
    const float* x_s   = (const float*)d_in[2];
    const float* Win_p = (const float*)d_in[3];
    const float* bin_p = (const float*)d_in[4];
    const float* Win_d = (const float*)d_in[5];
    const float* bin_d = (const float*)d_in[6];
    const float* Win_s = (const float*)d_in[7];
    const float* bin_s = (const float*)d_in[8];
    const float* Wk    = (const float*)d_in[9];
    const float* bk    = (const float*)d_in[10];
    const float* Wq    = (const float*)d_in[11];
    const float* bq    = (const float*)d_in[12];
    const float* Wv    = (const float*)d_in[13];
    const float* bv    = (const float*)d_in[14];
    const float* Wa    = (const float*)d_in[15];
    const float* ba    = (const float*)d_in[16];
    const float* a_rel = (const float*)d_in[17];
    const float* m_rel = (const float*)d_in[18];
    const float* p_rel = (const float*)d_in[19];
    const float* skip  = (const float*)d_in[20];
    const int*   ei_pd = (const int*)d_in[21];
    const int*   ei_dp = (const int*)d_in[22];
    const int*   ei_ds = (const int*)d_in[23];
    const int*   ei_ps = (const int*)d_in[24];
    float* out = (float*)d_out;

    float *px, *pq, *pkr, *pvr, *pnum, *pden, *pWc, *pbc;
    cudaGetSymbolAddress((void**)&px,   g_x);
    cudaGetSymbolAddress((void**)&pq,   g_q);
    cudaGetSymbolAddress((void**)&pkr,  g_krel);
    cudaGetSymbolAddress((void**)&pvr,  g_vrel);
    cudaGetSymbolAddress((void**)&pnum, g_num);
    cudaGetSymbolAddress((void**)&pden, g_den);
    cudaGetSymbolAddress((void**)&pWc,  g_Wc);
    cudaGetSymbolAddress((void**)&pbc,  g_bc);

    // fold a_rel/m_rel/p_rel/scale into K,V projection weights (per layer & relation)
    combine_weights<<<16, 256>>>(Wk, bk, Wv, bv, a_rel, m_rel, p_rel);

    // input projections -> g_x
    gemm64<64, 0><<<cdiv(N_P, 128), 128>>>(x_p, Win_p, bin_p, px, N_P,
        nullptr, nullptr, nullptr, nullptr, nullptr, nullptr);
    gemm64<128, 0><<<cdiv(N_D, 128), 128>>>(x_d, Win_d, bin_d, px + (size_t)N_P * 64, N_D,
        nullptr, nullptr, nullptr, nullptr, nullptr, nullptr);
    gemm64<64, 0><<<cdiv(N_S, 128), 128>>>(x_s, Win_s, bin_s, px + (size_t)(N_P + N_D) * 64, N_S,
        nullptr, nullptr, nullptr, nullptr, nullptr, nullptr);

    const int toff[3]  = {0, N_P, N_P + N_D};
    const int tN[3]    = {N_P, N_D, N_S};
    const int rst[4]   = {0, 1, 1, 0};
    const int kroff[4] = {0, N_P, N_P + N_D, N_P + 2 * N_D};
    const int rN[4]    = {N_P, N_D, N_D, N_P};

    for (int l = 0; l < 2; l++) {
        init_buffers<<<cdiv(DSTN_TOT * CD, 256), 256>>>();

        // Q projections per type
        for (int t = 0; t < 3; t++)
            gemm64<64, 0><<<cdiv(tN[t], 128), 128>>>(
                px + (size_t)toff[t] * 64,
                Wq + (size_t)(l * 3 + t) * 4096, bq + (size_t)(l * 3 + t) * 64,
                pq + (size_t)toff[t] * 64, tN[t],
                nullptr, nullptr, nullptr, nullptr, nullptr, nullptr);

        // relation-transformed K/V directly from x via combined weights
        for (int r = 0; r < 4; r++) {
            gemm64<64, 0><<<cdiv(rN[r], 128), 128>>>(
                px + (size_t)toff[rst[r]] * 64,
                pWc + (size_t)(l * 8 + r) * 4096, pbc + (size_t)(l * 8 + r) * 64,
                pkr + (size_t)kroff[r] * 64, rN[r],
                nullptr, nullptr, nullptr, nullptr, nullptr, nullptr);
            gemm64<64, 0><<<cdiv(rN[r], 128), 128>>>(
                px + (size_t)toff[rst[r]] * 64,
                pWc + (size_t)(l * 8 + 4 + r) * 4096, pbc + (size_t)(l * 8 + 4 + r) * 64,
                pvr + (size_t)kroff[r] * 64, rN[r],
                nullptr, nullptr, nullptr, nullptr, nullptr, nullptr);
        }

        edge_pass1<<<cdiv(ET * HD, 256), 256>>>(ei_pd, ei_dp, ei_ds, ei_ps);
        edge_pass2<<<cdiv(ET * HD, 256), 256>>>(ei_pd, ei_dp, ei_ds, ei_ps);

        float* Yb = (l == 0) ? px : out;
        // P (type 0): incoming relation r1 (num offset N_D)
        gemm64<64, 1><<<cdiv(N_P, 128), 128>>>(
            nullptr, Wa + (size_t)(l * 3 + 0) * 4096, ba + (size_t)(l * 3 + 0) * 64,
            Yb, N_P,
            pnum + (size_t)N_D * 64, pden + (size_t)N_D * 4, nullptr, nullptr,
            px, skip + l * 3 + 0);
        // D (type 1): incoming relation r0 (num offset 0)
        gemm64<64, 1><<<cdiv(N_D, 128), 128>>>(
            nullptr, Wa + (size_t)(l * 3 + 1) * 4096, ba + (size_t)(l * 3 + 1) * 64,
            Yb + (size_t)N_P * 64, N_D,
            pnum, pden, nullptr, nullptr,
            px + (size_t)N_P * 64, skip + l * 3 + 1);
        // S (type 2): incoming relations r2 and r3
        gemm64<64, 1><<<cdiv(N_S, 128), 128>>>(
            nullptr, Wa + (size_t)(l * 3 + 2) * 4096, ba + (size_t)(l * 3 + 2) * 64,
            Yb + (size_t)(N_P + N_D) * 64, N_S,
            pnum + (size_t)(N_D + N_P) * 64, pden + (size_t)(N_D + N_P) * 4,
            pnum + (size_t)(N_D + N_P + N_S) * 64, pden + (size_t)(N_D + N_P + N_S) * 4,
            px + (size_t)(N_P + N_D) * 64, skip + l * 3 + 2);
    }
    (void)in_sizes; (void)n_in; (void)out_size;
}

// round 2
// speedup vs baseline: 1.2272x; 1.2272x over previous
#include <cuda_runtime.h>
#include <math.h>

// ---------------- problem constants ----------------
#define N_P 100000
#define N_D 1000
#define N_S 5000
#define NT  (N_P + N_D + N_S)          // 106000
#define CD  64
#define HD  4
#define DHD 16
#define E0 300000
#define E1 300000
#define E2 100000
#define E3 100000
#define ET (E0 + E1 + E2 + E3)
#define KREL_TOT (2*N_P + 2*N_D)       // 202000
#define DSTN_TOT (N_D + N_P + 2*N_S)   // 111000

typedef unsigned long long u64;

// ---------------- device scratch ----------------
__device__ __align__(16) float g_x[NT * CD];
__device__ __align__(16) float g_q[NT * CD];
__device__ __align__(16) float g_krel[KREL_TOT * CD];
__device__ __align__(16) float g_vrel[KREL_TOT * CD];
__device__ __align__(16) float g_den[DSTN_TOT * HD];
__device__ __align__(16) float g_num[DSTN_TOT * CD];
__device__ __align__(16) float g_Wc[16 * CD * CD];   // [l][kv][r]
__device__ __align__(16) float g_bc[16 * CD];

// ---------------- f32x2 helpers (Blackwell packed fp32) ----------------
__device__ __forceinline__ u64 pack2(float x) {
    u64 r; asm("mov.b64 %0, {%1, %1};" : "=l"(r) : "f"(x)); return r;
}
__device__ __forceinline__ u64 fma2(u64 a, u64 b, u64 c) {
    u64 d; asm("fma.rn.f32x2 %0, %1, %2, %3;" : "=l"(d) : "l"(a), "l"(b), "l"(c)); return d;
}
__device__ __forceinline__ float2 unpack2(u64 a) {
    float2 f; asm("mov.b64 {%0, %1}, %2;" : "=f"(f.x), "=f"(f.y) : "l"(a)); return f;
}

// ---------------- combine weights:  Wc = W @ blockdiag(rel) * scale ----------------
__global__ void combine_weights(const float* __restrict__ Wk, const float* __restrict__ bk,
                                const float* __restrict__ Wv, const float* __restrict__ bv,
                                const float* __restrict__ a_rel, const float* __restrict__ m_rel,
                                const float* __restrict__ p_rel)
{
    int blk = blockIdx.x;
    int l  = blk >> 3;
    int kv = (blk >> 2) & 1;
    int r  = blk & 3;
    const int st_tab[4] = {0, 1, 1, 0};
    int st = st_tab[r];

    const float* Wbase = (kv == 0 ? Wk : Wv) + (size_t)(l*3 + st) * CD * CD;
    const float* bbase = (kv == 0 ? bk : bv) + (size_t)(l*3 + st) * CD;
    const float* rel   = (kv == 0 ? a_rel : m_rel) + (size_t)(l*4 + r) * HD * DHD * DHD;

    __shared__ float srel[HD * DHD * DHD];
    __shared__ float sscale[HD];
    int t = threadIdx.x; // 256
    for (int i = t; i < HD*DHD*DHD; i += 256) srel[i] = rel[i];
    if (t < HD) sscale[t] = (kv == 0) ? p_rel[(l*4 + r) * HD + t] * 0.25f : 1.0f;
    __syncthreads();

    float* Wc = g_Wc + (size_t)blk * CD * CD;
    float* bc = g_bc + (size_t)blk * CD;

    int c = t >> 2;
    int h = t & 3;
    float wrow[DHD];
#pragma unroll
    for (int d = 0; d < DHD; d++) wrow[d] = Wbase[c*CD + h*DHD + d];
    float sc = sscale[h];
#pragma unroll
    for (int e = 0; e < DHD; e++) {
        float s = 0.f;
#pragma unroll
        for (int d = 0; d < DHD; d++) s += wrow[d] * srel[h*256 + d*16 + e];
        Wc[c*CD + h*DHD + e] = s * sc;
    }
    if (t < CD) {
        int hh = t >> 4, ee = t & 15;
        float s = 0.f;
#pragma unroll
        for (int d = 0; d < DHD; d++) s += bbase[hh*DHD + d] * srel[hh*256 + d*16 + ee];
        bc[t] = s * sscale[hh];
    }
}

// ---------------- multi-tile output descriptor ----------------
struct Tile5 {
    const float* w[5];
    const float* b[5];
    float*       y[5];
};

// ---------------- GEMM: Y[ti][M,64] = op(X)[M,KDIM] @ W[ti][KDIM,64] + b[ti] ----------------
// MODE 0: X from memory. MODE 1: X = gelu(num0/den0 (+num1/den1)); skip-gate epilogue.
// f32x2 packed FMA inner loop (2x fp32 throughput on fma pipe).
template<int KDIM, int MODE>
__global__ void __launch_bounds__(128)
gemm64v(const float* __restrict__ X, Tile5 P, int M,
        const float* __restrict__ num0, const float* __restrict__ den0,
        const float* __restrict__ num1, const float* __restrict__ den1,
        const float* __restrict__ xold, const float* __restrict__ skipp)
{
    __shared__ float Xs[128 * 17];
    __shared__ __align__(16) float Ws[16 * 64];
    const int t  = threadIdx.x;
    const int m0 = blockIdx.x * 128;
    const int ti = blockIdx.y;
    const float* __restrict__ W    = P.w[ti];
    const float* __restrict__ bias = P.b[ti];
    float* __restrict__ Y          = P.y[ti];
    const int ty = t >> 3;   // 0..15
    const int tx = t & 7;    // 0..7

    u64 acc[8][4];
#pragma unroll
    for (int i = 0; i < 8; i++)
#pragma unroll
        for (int j = 0; j < 4; j++) acc[i][j] = 0ull;

    for (int k0 = 0; k0 < KDIM; k0 += 16) {
        if (MODE == 0) {
#pragma unroll
            for (int i = 0; i < 4; i++) {
                int f4  = t + i * 128;
                int row = f4 >> 2, c4 = f4 & 3;
                float4 v = make_float4(0.f, 0.f, 0.f, 0.f);
                if (m0 + row < M)
                    v = *(const float4*)&X[(size_t)(m0 + row) * KDIM + k0 + c4 * 4];
                float* d = &Xs[row * 17 + c4 * 4];
                d[0] = v.x; d[1] = v.y; d[2] = v.z; d[3] = v.w;
            }
        } else {
#pragma unroll
            for (int i = 0; i < 16; i++) {
                int idx = t + i * 128;
                int row = idx >> 4, cc = idx & 15;
                float val = 0.f;
                int n = m0 + row;
                if (n < M) {
                    int c = k0 + cc;
                    int h = c >> 4;
                    val = num0[(size_t)n * 64 + c] / (den0[(size_t)n * 4 + h] + 1e-16f);
                    if (num1)
                        val += num1[(size_t)n * 64 + c] / (den1[(size_t)n * 4 + h] + 1e-16f);
                    val = 0.5f * val * (1.0f + erff(val * 0.70710678118654752f));
                }
                Xs[row * 17 + cc] = val;
            }
        }
#pragma unroll
        for (int i = 0; i < 2; i++) {
            int f4 = t + i * 128;
            int wr = f4 >> 4, c4 = f4 & 15;
            *(float4*)&Ws[wr * 64 + c4 * 4] = *(const float4*)&W[(size_t)(k0 + wr) * 64 + c4 * 4];
        }
        __syncthreads();
#pragma unroll
        for (int kk = 0; kk < 16; kk++) {
            const u64* wp = (const u64*)&Ws[kk * 64 + tx * 8];
            u64 w0 = wp[0], w1 = wp[1], w2 = wp[2], w3 = wp[3];
#pragma unroll
            for (int i = 0; i < 8; i++) {
                u64 x2 = pack2(Xs[(ty + i * 16) * 17 + kk]);
                acc[i][0] = fma2(x2, w0, acc[i][0]);
                acc[i][1] = fma2(x2, w1, acc[i][1]);
                acc[i][2] = fma2(x2, w2, acc[i][2]);
                acc[i][3] = fma2(x2, w3, acc[i][3]);
            }
        }
        __syncthreads();
    }

    float bb[8];
#pragma unroll
    for (int j = 0; j < 8; j++) bb[j] = bias[tx * 8 + j];
    float s = 0.f;
    if (MODE == 1) s = 1.0f / (1.0f + expf(-skipp[0]));

#pragma unroll
    for (int i = 0; i < 8; i++) {
        int row = m0 + ty + i * 16;
        if (row < M) {
            float o[8];
#pragma unroll
            for (int j = 0; j < 4; j++) {
                float2 p = unpack2(acc[i][j]);
                o[2*j]   = p.x + bb[2*j];
                o[2*j+1] = p.y + bb[2*j+1];
            }
            if (MODE == 1) {
                float4 x0 = *(const float4*)&xold[(size_t)row * 64 + tx * 8];
                float4 x1 = *(const float4*)&xold[(size_t)row * 64 + tx * 8 + 4];
                float om = 1.0f - s;
                o[0] = s*o[0] + om*x0.x; o[1] = s*o[1] + om*x0.y;
                o[2] = s*o[2] + om*x0.z; o[3] = s*o[3] + om*x0.w;
                o[4] = s*o[4] + om*x1.x; o[5] = s*o[5] + om*x1.y;
                o[6] = s*o[6] + om*x1.z; o[7] = s*o[7] + om*x1.w;
            }
            *(float4*)&Y[(size_t)row * 64 + tx * 8]     = make_float4(o[0], o[1], o[2], o[3]);
            *(float4*)&Y[(size_t)row * 64 + tx * 8 + 4] = make_float4(o[4], o[5], o[6], o[7]);
        }
    }
}

// ---------------- fused single-pass edge kernel (per relation) ----------------
// Softmax shift-invariance: exp(a)/(sum exp(a)) == exp(a-mx)/(sum exp(a-mx)); the
// +1e-16 eps stays negligible since den >> 1e-16. Clamp at 60 guards fp32 overflow.
template<int QOFF, int KVOFF, int DNOFF>
__global__ void edge_fused(const int* __restrict__ ei, int E)
{
    int gid = blockIdx.x * blockDim.x + threadIdx.x;
    if (gid >= E * HD) return;
    int e = gid >> 2, h = gid & 3;
    int src = __ldg(&ei[e]);
    int dst = __ldg(&ei[E + e]);

    const float4* qp = (const float4*)&g_q[(size_t)(QOFF + dst) * 64 + h * 16];
    const float4* kp = (const float4*)&g_krel[(size_t)(KVOFF + src) * 64 + h * 16];
    float a = 0.f;
#pragma unroll
    for (int j = 0; j < 4; j++) {
        float4 q4 = qp[j], k4 = kp[j];
        a += q4.x * k4.x + q4.y * k4.y + q4.z * k4.z + q4.w * k4.w;
    }
    float w = expf(fminf(a, 60.f));
    atomicAdd(&g_den[(size_t)(DNOFF + dst) * 4 + h], w);

    const float4* vp = (const float4*)&g_vrel[(size_t)(KVOFF + src) * 64 + h * 16];
    float4* np = (float4*)&g_num[(size_t)(DNOFF + dst) * 64 + h * 16];
#pragma unroll
    for (int j = 0; j < 4; j++) {
        float4 v4 = vp[j];
        atomicAdd(&np[j], make_float4(v4.x * w, v4.y * w, v4.z * w, v4.w * w));
    }
}

// ---------------- buffer init ----------------
__global__ void init_buffers()
{
    int i = blockIdx.x * blockDim.x + threadIdx.x;
    if (i < DSTN_TOT * HD) g_den[i] = 0.f;
    if (i < DSTN_TOT * CD) g_num[i] = 0.f;
}

// ---------------- host orchestration ----------------
static inline int cdiv(int a, int b) { return (a + b - 1) / b; }

extern "C" void kernel_launch(void* const* d_in, const int* in_sizes, int n_in,
                              void* d_out, int out_size)
{
    const float* x_p   = (const float*)d_in[0];
    const float* x_d   = (const float*)d_in[1];
    const float* x_s   = (const float*)d_in[2];
    const float* Win_p = (const float*)d_in[3];
    const float* bin_p = (const float*)d_in[4];
    const float* Win_d = (const float*)d_in[5];
    const float* bin_d = (const float*)d_in[6];
    const float* Win_s = (const float*)d_in[7];
    const float* bin_s = (const float*)d_in[8];
    const float* Wk    = (const float*)d_in[9];
    const float* bk    = (const float*)d_in[10];
    const float* Wq    = (const float*)d_in[11];
    const float* bq    = (const float*)d_in[12];
    const float* Wv    = (const float*)d_in[13];
    const float* bv    = (const float*)d_in[14];
    const float* Wa    = (const float*)d_in[15];
    const float* ba    = (const float*)d_in[16];
    const float* a_rel = (const float*)d_in[17];
    const float* m_rel = (const float*)d_in[18];
    const float* p_rel = (const float*)d_in[19];
    const float* skip  = (const float*)d_in[20];
    const int*   ei_pd = (const int*)d_in[21];
    const int*   ei_dp = (const int*)d_in[22];
    const int*   ei_ds = (const int*)d_in[23];
    const int*   ei_ps = (const int*)d_in[24];
    float* out = (float*)d_out;

    float *px, *pq, *pkr, *pvr, *pnum, *pden, *pWc, *pbc;
    cudaGetSymbolAddress((void**)&px,   g_x);
    cudaGetSymbolAddress((void**)&pq,   g_q);
    cudaGetSymbolAddress((void**)&pkr,  g_krel);
    cudaGetSymbolAddress((void**)&pvr,  g_vrel);
    cudaGetSymbolAddress((void**)&pnum, g_num);
    cudaGetSymbolAddress((void**)&pden, g_den);
    cudaGetSymbolAddress((void**)&pWc,  g_Wc);
    cudaGetSymbolAddress((void**)&pbc,  g_bc);

    combine_weights<<<16, 256>>>(Wk, bk, Wv, bv, a_rel, m_rel, p_rel);

    // input projections
    {
        Tile5 T{}; T.w[0]=Win_p; T.b[0]=bin_p; T.y[0]=px;
        gemm64v<64,0><<<dim3(cdiv(N_P,128),1), 128>>>(x_p, T, N_P, 0,0,0,0,0,0);
    }
    {
        Tile5 T{}; T.w[0]=Win_d; T.b[0]=bin_d; T.y[0]=px + (size_t)N_P*64;
        gemm64v<128,0><<<dim3(cdiv(N_D,128),1), 128>>>(x_d, T, N_D, 0,0,0,0,0,0);
    }
    {
        Tile5 T{}; T.w[0]=Win_s; T.b[0]=bin_s; T.y[0]=px + (size_t)(N_P+N_D)*64;
        gemm64v<64,0><<<dim3(cdiv(N_S,128),1), 128>>>(x_s, T, N_S, 0,0,0,0,0,0);
    }

    // krel/vrel node-offsets per relation
    const size_t kr0 = 0, kr1 = N_P, kr2 = N_P + N_D, kr3 = N_P + 2*N_D;

    for (int l = 0; l < 2; l++) {
        init_buffers<<<cdiv(DSTN_TOT * CD, 256), 256>>>();

        // patients (type 0): Q | krel r0 | vrel r0 | krel r3 | vrel r3
        {
            Tile5 T;
            T.w[0]=Wq + (size_t)(l*3+0)*4096;  T.b[0]=bq + (size_t)(l*3+0)*64;  T.y[0]=pq;
            T.w[1]=pWc + (size_t)(l*8+0)*4096; T.b[1]=pbc + (size_t)(l*8+0)*64; T.y[1]=pkr + kr0*64;
            T.w[2]=pWc + (size_t)(l*8+4)*4096; T.b[2]=pbc + (size_t)(l*8+4)*64; T.y[2]=pvr + kr0*64;
            T.w[3]=pWc + (size_t)(l*8+3)*4096; T.b[3]=pbc + (size_t)(l*8+3)*64; T.y[3]=pkr + kr3*64;
            T.w[4]=pWc + (size_t)(l*8+7)*4096; T.b[4]=pbc + (size_t)(l*8+7)*64; T.y[4]=pvr + kr3*64;
            gemm64v<64,0><<<dim3(cdiv(N_P,128),5), 128>>>(px, T, N_P, 0,0,0,0,0,0);
        }
        // drugs (type 1): Q | krel r1 | vrel r1 | krel r2 | vrel r2
        {
            Tile5 T;
            const float* xd = px + (size_t)N_P*64;
            T.w[0]=Wq + (size_t)(l*3+1)*4096;  T.b[0]=bq + (size_t)(l*3+1)*64;  T.y[0]=pq + (size_t)N_P*64;
            T.w[1]=pWc + (size_t)(l*8+1)*4096; T.b[1]=pbc + (size_t)(l*8+1)*64; T.y[1]=pkr + kr1*64;
            T.w[2]=pWc + (size_t)(l*8+5)*4096; T.b[2]=pbc + (size_t)(l*8+5)*64; T.y[2]=pvr + kr1*64;
            T.w[3]=pWc + (size_t)(l*8+2)*4096; T.b[3]=pbc + (size_t)(l*8+2)*64; T.y[3]=pkr + kr2*64;
            T.w[4]=pWc + (size_t)(l*8+6)*4096; T.b[4]=pbc + (size_t)(l*8+6)*64; T.y[4]=pvr + kr2*64;
            gemm64v<64,0><<<dim3(cdiv(N_D,128),5), 128>>>(xd, T, N_D, 0,0,0,0,0,0);
        }
        // diseases (type 2): Q only
        {
            Tile5 T{};
            T.w[0]=Wq + (size_t)(l*3+2)*4096; T.b[0]=bq + (size_t)(l*3+2)*64;
            T.y[0]=pq + (size_t)(N_P+N_D)*64;
            gemm64v<64,0><<<dim3(cdiv(N_S,128),5-4), 128>>>(px + (size_t)(N_P+N_D)*64, T, N_S, 0,0,0,0,0,0);
        }

        // single-pass softmax-attention edge kernels (per relation)
        edge_fused<N_P,       0,              0               ><<<cdiv(E0*HD,256),256>>>(ei_pd, E0);
        edge_fused<0,         N_P,            N_D             ><<<cdiv(E1*HD,256),256>>>(ei_dp, E1);
        edge_fused<N_P+N_D,   N_P+N_D,        N_D+N_P         ><<<cdiv(E2*HD,256),256>>>(ei_ds, E2);
        edge_fused<N_P+N_D,   N_P+2*N_D,      N_D+N_P+N_S     ><<<cdiv(E3*HD,256),256>>>(ei_ps, E3);

        float* Yb = (l == 0) ? px : out;
        // P epilogue (incoming r1, dn offset N_D)
        {
            Tile5 T{};
            T.w[0]=Wa + (size_t)(l*3+0)*4096; T.b[0]=ba + (size_t)(l*3+0)*64; T.y[0]=Yb;
            gemm64v<64,1><<<dim3(cdiv(N_P,128),1), 128>>>(nullptr, T, N_P,
                pnum + (size_t)N_D*64, pden + (size_t)N_D*4, nullptr, nullptr,
                px, skip + l*3 + 0);
        }
        // D epilogue (incoming r0, dn offset 0)
        {
            Tile5 T{};
            T.w[0]=Wa + (size_t)(l*3+1)*4096; T.b[0]=ba + (size_t)(l*3+1)*64;
            T.y[0]=Yb + (size_t)N_P*64;
            gemm64v<64,1><<<dim3(cdiv(N_D,128),1), 128>>>(nullptr, T, N_D,
                pnum, pden, nullptr, nullptr,
                px + (size_t)N_P*64, skip + l*3 + 1);
        }
        // S epilogue (incoming r2 + r3)
        {
            Tile5 T{};
            T.w[0]=Wa + (size_t)(l*3+2)*4096; T.b[0]=ba + (size_t)(l*3+2)*64;
            T.y[0]=Yb + (size_t)(N_P+N_D)*64;
            gemm64v<64,1><<<dim3(cdiv(N_S,128),1), 128>>>(nullptr, T, N_S,
                pnum + (size_t)(N_D+N_P)*64, pden + (size_t)(N_D+N_P)*4,
                pnum + (size_t)(N_D+N_P+N_S)*64, pden + (size_t)(N_D+N_P+N_S)*4,
                px + (size_t)(N_P+N_D)*64, skip + l*3 + 2);
        }
    }
    (void)in_sizes; (void)n_in; (void)out_size;
}

// round 3
// speedup vs baseline: 1.6986x; 1.3841x over previous
#include <cuda_runtime.h>
#include <math.h>

// ---------------- problem constants ----------------
#define N_P 100000
#define N_D 1000
#define N_S 5000
#define NT  (N_P + N_D + N_S)
#define CD  64
#define HD  4
#define E0 300000
#define E1 300000
#define E2 100000
#define E3 100000
#define ET (E0 + E1 + E2 + E3)
#define KREL_TOT (2*N_P + 2*N_D)
#define DSTN_TOT (N_D + N_P + 2*N_S)

typedef unsigned long long u64;

// ---------------- device scratch ----------------
__device__ __align__(16) float g_x[NT * CD];
__device__ __align__(16) float g_q[NT * CD];
__device__ __align__(16) float g_krel[KREL_TOT * CD];
__device__ __align__(16) float g_vrel[KREL_TOT * CD];
__device__ __align__(16) float g_den[DSTN_TOT * HD];
__device__ __align__(16) float g_num[DSTN_TOT * CD];
__device__ __align__(16) float g_Wc[16 * CD * CD];
__device__ __align__(16) float g_bc[16 * CD];

// ---------------- f32x2 helpers ----------------
__device__ __forceinline__ u64 pack2(float x) {
    u64 r; asm("mov.b64 %0, {%1, %1};" : "=l"(r) : "f"(x)); return r;
}
__device__ __forceinline__ u64 fma2(u64 a, u64 b, u64 c) {
    u64 d; asm("fma.rn.f32x2 %0, %1, %2, %3;" : "=l"(d) : "l"(a), "l"(b), "l"(c)); return d;
}
__device__ __forceinline__ float2 unpack2(u64 a) {
    float2 f; asm("mov.b64 {%0, %1}, %2;" : "=f"(f.x), "=f"(f.y) : "l"(a)); return f;
}

// ---------------- combine weights:  Wc = W @ blockdiag(rel) * scale ----------------
__global__ void combine_weights(const float* __restrict__ Wk, const float* __restrict__ bk,
                                const float* __restrict__ Wv, const float* __restrict__ bv,
                                const float* __restrict__ a_rel, const float* __restrict__ m_rel,
                                const float* __restrict__ p_rel)
{
    int blk = blockIdx.x;
    int l  = blk >> 3;
    int kv = (blk >> 2) & 1;
    int r  = blk & 3;
    const int st_tab[4] = {0, 1, 1, 0};
    int st = st_tab[r];

    const float* Wbase = (kv == 0 ? Wk : Wv) + (size_t)(l*3 + st) * CD * CD;
    const float* bbase = (kv == 0 ? bk : bv) + (size_t)(l*3 + st) * CD;
    const float* rel   = (kv == 0 ? a_rel : m_rel) + (size_t)(l*4 + r) * HD * 16 * 16;

    __shared__ float srel[HD * 16 * 16];
    __shared__ float sscale[HD];
    int t = threadIdx.x; // 256
    for (int i = t; i < HD*256; i += 256) srel[i] = rel[i];
    if (t < HD) sscale[t] = (kv == 0) ? p_rel[(l*4 + r) * HD + t] * 0.25f : 1.0f;
    __syncthreads();

    float* Wc = g_Wc + (size_t)blk * CD * CD;
    float* bc = g_bc + (size_t)blk * CD;

    int c = t >> 2, h = t & 3;
    float wrow[16];
#pragma unroll
    for (int d = 0; d < 16; d++) wrow[d] = Wbase[c*CD + h*16 + d];
    float sc = sscale[h];
#pragma unroll
    for (int e = 0; e < 16; e++) {
        float s = 0.f;
#pragma unroll
        for (int d = 0; d < 16; d++) s += wrow[d] * srel[h*256 + d*16 + e];
        Wc[c*CD + h*16 + e] = s * sc;
    }
    if (t < CD) {
        int hh = t >> 4, ee = t & 15;
        float s = 0.f;
#pragma unroll
        for (int d = 0; d < 16; d++) s += bbase[hh*16 + d] * srel[hh*256 + d*16 + ee];
        bc[t] = s * sscale[hh];
    }
}

// ---------------- job descriptors ----------------
struct TileW { const float* W; const float* b; float* Y; };
struct JobA  { const float* X; int M; int blk0; int nT; TileW tl[5]; };
struct ParamsA { JobA job[3]; };

struct JobE {
    const float* num0; const float* den0;
    const float* num1; const float* den1;
    const float* xold; const float* skipp;
    const float* W; const float* b; float* Y;
    int M; int blk0;
};
struct ParamsE { JobE job[3]; };

struct JobI { const float* X; const float* W; const float* b; float* Y; int M; int blk0; int K; };
struct ParamsI { JobI job[3]; };

// ---------------- Phase A: multi-tile projection GEMM (K=64) ----------------
// One launch covers all node types; each block loads its X tile once and loops
// over up to 5 weight matrices (Q, krel/vrel per relation).
__global__ void __launch_bounds__(128)
gemm_phaseA(ParamsA P)
{
    __shared__ float Xs[128 * 65];
    __shared__ __align__(16) float Ws[64 * 64];
    int bx = blockIdx.x;
    int j = (bx >= P.job[2].blk0) ? 2 : (bx >= P.job[1].blk0) ? 1 : 0;
    const JobA& J = P.job[j];
    int m0 = (bx - J.blk0) * 128;
    int t = threadIdx.x;
    const int ty = t >> 3, tx = t & 7;

    // load X tile once
#pragma unroll
    for (int i = 0; i < 16; i++) {
        int f4 = t + i * 128;          // 0..2047
        int row = f4 >> 4, c4 = f4 & 15;
        float4 v = make_float4(0.f, 0.f, 0.f, 0.f);
        if (m0 + row < J.M) v = *(const float4*)&J.X[(size_t)(m0 + row) * 64 + c4 * 4];
        float* d = &Xs[row * 65 + c4 * 4];
        d[0] = v.x; d[1] = v.y; d[2] = v.z; d[3] = v.w;
    }

    for (int ti = 0; ti < J.nT; ti++) {
        __syncthreads();               // Xs ready (ti=0) / Ws safe to overwrite
        const float* __restrict__ W = J.tl[ti].W;
#pragma unroll
        for (int i = 0; i < 8; i++) {
            int f4 = (t + i * 128) * 4;
            *(float4*)&Ws[f4] = *(const float4*)&W[f4];
        }
        __syncthreads();

        u64 acc[8][4];
#pragma unroll
        for (int i = 0; i < 8; i++)
#pragma unroll
            for (int k = 0; k < 4; k++) acc[i][k] = 0ull;

#pragma unroll 16
        for (int kk = 0; kk < 64; kk++) {
            const u64* wp = (const u64*)&Ws[kk * 64 + tx * 8];
            u64 w0 = wp[0], w1 = wp[1], w2 = wp[2], w3 = wp[3];
#pragma unroll
            for (int i = 0; i < 8; i++) {
                u64 x2 = pack2(Xs[(ty + i * 16) * 65 + kk]);
                acc[i][0] = fma2(x2, w0, acc[i][0]);
                acc[i][1] = fma2(x2, w1, acc[i][1]);
                acc[i][2] = fma2(x2, w2, acc[i][2]);
                acc[i][3] = fma2(x2, w3, acc[i][3]);
            }
        }

        const float* bias = J.tl[ti].b;
        float* Y = J.tl[ti].Y;
        float bb[8];
#pragma unroll
        for (int q = 0; q < 8; q++) bb[q] = bias[tx * 8 + q];
#pragma unroll
        for (int i = 0; i < 8; i++) {
            int row = m0 + ty + i * 16;
            if (row < J.M) {
                float o[8];
#pragma unroll
                for (int k = 0; k < 4; k++) {
                    float2 p = unpack2(acc[i][k]);
                    o[2*k] = p.x + bb[2*k]; o[2*k+1] = p.y + bb[2*k+1];
                }
                *(float4*)&Y[(size_t)row * 64 + tx * 8]     = make_float4(o[0], o[1], o[2], o[3]);
                *(float4*)&Y[(size_t)row * 64 + tx * 8 + 4] = make_float4(o[4], o[5], o[6], o[7]);
            }
        }
    }
}

// ---------------- Epilogue: gelu(softmax-out) @ Wa + skip gate ----------------
__global__ void __launch_bounds__(128)
gemm_epilogue(ParamsE P)
{
    __shared__ float Xs[128 * 65];
    __shared__ __align__(16) float Ws[64 * 64];
    int bx = blockIdx.x;
    int j = (bx >= P.job[2].blk0) ? 2 : (bx >= P.job[1].blk0) ? 1 : 0;
    const JobE& J = P.job[j];
    int m0 = (bx - J.blk0) * 128;
    int t = threadIdx.x;
    const int ty = t >> 3, tx = t & 7;

    // build gelu(num/den) tile
#pragma unroll
    for (int i = 0; i < 32; i++) {
        int idx = t + i * 128;         // 0..4095
        int row = idx >> 5, cc = idx & 31;  // 2 cols per slot? no: 128*64=8192
        (void)row; (void)cc;
    }
    // 8192 elements / 128 threads = 64 each
#pragma unroll
    for (int i = 0; i < 64; i++) {
        int idx = t + i * 128;
        int row = idx >> 6, cc = idx & 63;
        float val = 0.f;
        int n = m0 + row;
        if (n < J.M) {
            int h = cc >> 4;
            val = J.num0[(size_t)n * 64 + cc] / (J.den0[(size_t)n * 4 + h] + 1e-16f);
            if (J.num1)
                val += J.num1[(size_t)n * 64 + cc] / (J.den1[(size_t)n * 4 + h] + 1e-16f);
            val = 0.5f * val * (1.0f + erff(val * 0.70710678118654752f));
        }
        Xs[row * 65 + cc] = val;
    }
#pragma unroll
    for (int i = 0; i < 8; i++) {
        int f4 = (t + i * 128) * 4;
        *(float4*)&Ws[f4] = *(const float4*)&J.W[f4];
    }
    __syncthreads();

    u64 acc[8][4];
#pragma unroll
    for (int i = 0; i < 8; i++)
#pragma unroll
        for (int k = 0; k < 4; k++) acc[i][k] = 0ull;

#pragma unroll 16
    for (int kk = 0; kk < 64; kk++) {
        const u64* wp = (const u64*)&Ws[kk * 64 + tx * 8];
        u64 w0 = wp[0], w1 = wp[1], w2 = wp[2], w3 = wp[3];
#pragma unroll
        for (int i = 0; i < 8; i++) {
            u64 x2 = pack2(Xs[(ty + i * 16) * 65 + kk]);
            acc[i][0] = fma2(x2, w0, acc[i][0]);
            acc[i][1] = fma2(x2, w1, acc[i][1]);
            acc[i][2] = fma2(x2, w2, acc[i][2]);
            acc[i][3] = fma2(x2, w3, acc[i][3]);
        }
    }

    float bb[8];
#pragma unroll
    for (int q = 0; q < 8; q++) bb[q] = J.b[tx * 8 + q];
    float s = 1.0f / (1.0f + expf(-J.skipp[0]));
    float om = 1.0f - s;

#pragma unroll
    for (int i = 0; i < 8; i++) {
        int row = m0 + ty + i * 16;
        if (row < J.M) {
            float o[8];
#pragma unroll
            for (int k = 0; k < 4; k++) {
                float2 p = unpack2(acc[i][k]);
                o[2*k] = p.x + bb[2*k]; o[2*k+1] = p.y + bb[2*k+1];
            }
            float4 x0 = *(const float4*)&J.xold[(size_t)row * 64 + tx * 8];
            float4 x1 = *(const float4*)&J.xold[(size_t)row * 64 + tx * 8 + 4];
            o[0] = s*o[0] + om*x0.x; o[1] = s*o[1] + om*x0.y;
            o[2] = s*o[2] + om*x0.z; o[3] = s*o[3] + om*x0.w;
            o[4] = s*o[4] + om*x1.x; o[5] = s*o[5] + om*x1.y;
            o[6] = s*o[6] + om*x1.z; o[7] = s*o[7] + om*x1.w;
            *(float4*)&J.Y[(size_t)row * 64 + tx * 8]     = make_float4(o[0], o[1], o[2], o[3]);
            *(float4*)&J.Y[(size_t)row * 64 + tx * 8 + 4] = make_float4(o[4], o[5], o[6], o[7]);
        }
    }
}

// ---------------- Input projections (runtime K: 64 or 128) ----------------
__global__ void __launch_bounds__(128)
gemm_input(ParamsI P)
{
    __shared__ float Xs[128 * 65];
    __shared__ __align__(16) float Ws[64 * 64];
    int bx = blockIdx.x;
    int j = (bx >= P.job[2].blk0) ? 2 : (bx >= P.job[1].blk0) ? 1 : 0;
    const JobI& J = P.job[j];
    int m0 = (bx - J.blk0) * 128;
    int t = threadIdx.x;
    const int ty = t >> 3, tx = t & 7;
    const int K = J.K;

    u64 acc[8][4];
#pragma unroll
    for (int i = 0; i < 8; i++)
#pragma unroll
        for (int k = 0; k < 4; k++) acc[i][k] = 0ull;

    for (int k0 = 0; k0 < K; k0 += 64) {
        __syncthreads();
#pragma unroll
        for (int i = 0; i < 16; i++) {
            int f4 = t + i * 128;
            int row = f4 >> 4, c4 = f4 & 15;
            float4 v = make_float4(0.f, 0.f, 0.f, 0.f);
            if (m0 + row < J.M) v = *(const float4*)&J.X[(size_t)(m0 + row) * K + k0 + c4 * 4];
            float* d = &Xs[row * 65 + c4 * 4];
            d[0] = v.x; d[1] = v.y; d[2] = v.z; d[3] = v.w;
        }
#pragma unroll
        for (int i = 0; i < 8; i++) {
            int f4 = (t + i * 128) * 4;
            *(float4*)&Ws[f4] = *(const float4*)&J.W[(size_t)k0 * 64 + f4];
        }
        __syncthreads();
#pragma unroll 16
        for (int kk = 0; kk < 64; kk++) {
            const u64* wp = (const u64*)&Ws[kk * 64 + tx * 8];
            u64 w0 = wp[0], w1 = wp[1], w2 = wp[2], w3 = wp[3];
#pragma unroll
            for (int i = 0; i < 8; i++) {
                u64 x2 = pack2(Xs[(ty + i * 16) * 65 + kk]);
                acc[i][0] = fma2(x2, w0, acc[i][0]);
                acc[i][1] = fma2(x2, w1, acc[i][1]);
                acc[i][2] = fma2(x2, w2, acc[i][2]);
                acc[i][3] = fma2(x2, w3, acc[i][3]);
            }
        }
    }

    float bb[8];
#pragma unroll
    for (int q = 0; q < 8; q++) bb[q] = J.b[tx * 8 + q];
#pragma unroll
    for (int i = 0; i < 8; i++) {
        int row = m0 + ty + i * 16;
        if (row < J.M) {
            float o[8];
#pragma unroll
            for (int k = 0; k < 4; k++) {
                float2 p = unpack2(acc[i][k]);
                o[2*k] = p.x + bb[2*k]; o[2*k+1] = p.y + bb[2*k+1];
            }
            *(float4*)&J.Y[(size_t)row * 64 + tx * 8]     = make_float4(o[0], o[1], o[2], o[3]);
            *(float4*)&J.Y[(size_t)row * 64 + tx * 8 + 4] = make_float4(o[4], o[5], o[6], o[7]);
        }
    }
}

// ---------------- merged single-pass edge kernel ----------------
// Softmax is shift-invariant; exp clamped at 60 to guard overflow (den >> eps).
__global__ void edge_all(const int* __restrict__ ei0, const int* __restrict__ ei1,
                         const int* __restrict__ ei2, const int* __restrict__ ei3)
{
    int gid = blockIdx.x * blockDim.x + threadIdx.x;
    if (gid >= ET * HD) return;
    int e = gid >> 2, h = gid & 3;

    const int* ei; int er, E, kvoff, qoff, dnoff;
    if (e < E0)                 { ei = ei0; er = e;            E = E0; kvoff = 0;           qoff = N_P;     dnoff = 0; }
    else if (e < E0+E1)         { ei = ei1; er = e - E0;       E = E1; kvoff = N_P;         qoff = 0;       dnoff = N_D; }
    else if (e < E0+E1+E2)      { ei = ei2; er = e - (E0+E1);  E = E2; kvoff = N_P+N_D;     qoff = N_P+N_D; dnoff = N_D+N_P; }
    else                        { ei = ei3; er = e-(E0+E1+E2); E = E3; kvoff = N_P+2*N_D;   qoff = N_P+N_D; dnoff = N_D+N_P+N_S; }

    int src = __ldg(&ei[er]);
    int dst = __ldg(&ei[E + er]);

    const float4* qp = (const float4*)&g_q[(size_t)(qoff + dst) * 64 + h * 16];
    const float4* kp = (const float4*)&g_krel[(size_t)(kvoff + src) * 64 + h * 16];
    float a = 0.f;
#pragma unroll
    for (int jj = 0; jj < 4; jj++) {
        float4 q4 = qp[jj], k4 = kp[jj];
        a += q4.x * k4.x + q4.y * k4.y + q4.z * k4.z + q4.w * k4.w;
    }
    float w = expf(fminf(a, 60.f));
    atomicAdd(&g_den[(size_t)(dnoff + dst) * 4 + h], w);

    const float4* vp = (const float4*)&g_vrel[(size_t)(kvoff + src) * 64 + h * 16];
    float4* np = (float4*)&g_num[(size_t)(dnoff + dst) * 64 + h * 16];
#pragma unroll
    for (int jj = 0; jj < 4; jj++) {
        float4 v4 = vp[jj];
        atomicAdd(&np[jj], make_float4(v4.x * w, v4.y * w, v4.z * w, v4.w * w));
    }
}

// ---------------- buffer init ----------------
__global__ void init_buffers()
{
    int i = blockIdx.x * blockDim.x + threadIdx.x;
    if (i < DSTN_TOT * HD) g_den[i] = 0.f;
    if (i < DSTN_TOT * CD) g_num[i] = 0.f;
}

// ---------------- host orchestration ----------------
static inline int cdiv(int a, int b) { return (a + b - 1) / b; }

extern "C" void kernel_launch(void* const* d_in, const int* in_sizes, int n_in,
                              void* d_out, int out_size)
{
    const float* x_p   = (const float*)d_in[0];
    const float* x_d   = (const float*)d_in[1];
    const float* x_s   = (const float*)d_in[2];
    const float* Win_p = (const float*)d_in[3];
    const float* bin_p = (const float*)d_in[4];
    const float* Win_d = (const float*)d_in[5];
    const float* bin_d = (const float*)d_in[6];
    const float* Win_s = (const float*)d_in[7];
    const float* bin_s = (const float*)d_in[8];
    const float* Wk    = (const float*)d_in[9];
    const float* bk    = (const float*)d_in[10];
    const float* Wq    = (const float*)d_in[11];
    const float* bq    = (const float*)d_in[12];
    const float* Wv    = (const float*)d_in[13];
    const float* bv    = (const float*)d_in[14];
    const float* Wa    = (const float*)d_in[15];
    const float* ba    = (const float*)d_in[16];
    const float* a_rel = (const float*)d_in[17];
    const float* m_rel = (const float*)d_in[18];
    const float* p_rel = (const float*)d_in[19];
    const float* skip  = (const float*)d_in[20];
    const int*   ei_pd = (const int*)d_in[21];
    const int*   ei_dp = (const int*)d_in[22];
    const int*   ei_ds = (const int*)d_in[23];
    const int*   ei_ps = (const int*)d_in[24];
    float* out = (float*)d_out;

    float *px, *pq, *pkr, *pvr, *pnum, *pden, *pWc, *pbc;
    cudaGetSymbolAddress((void**)&px,   g_x);
    cudaGetSymbolAddress((void**)&pq,   g_q);
    cudaGetSymbolAddress((void**)&pkr,  g_krel);
    cudaGetSymbolAddress((void**)&pvr,  g_vrel);
    cudaGetSymbolAddress((void**)&pnum, g_num);
    cudaGetSymbolAddress((void**)&pden, g_den);
    cudaGetSymbolAddress((void**)&pWc,  g_Wc);
    cudaGetSymbolAddress((void**)&pbc,  g_bc);

    const int BP = cdiv(N_P, 128);          // 782
    const int BD = cdiv(N_D, 128);          // 8
    const int BS = cdiv(N_S, 128);          // 40
    const size_t kr0 = 0, kr1 = N_P, kr2 = N_P + N_D, kr3 = N_P + 2*N_D;

    combine_weights<<<16, 256>>>(Wk, bk, Wv, bv, a_rel, m_rel, p_rel);

    // input projections (one launch, 3 jobs)
    {
        ParamsI P;
        P.job[0] = { x_p, Win_p, bin_p, px,                        N_P, 0,       64 };
        P.job[1] = { x_d, Win_d, bin_d, px + (size_t)N_P*64,       N_D, BP,      128 };
        P.job[2] = { x_s, Win_s, bin_s, px + (size_t)(N_P+N_D)*64, N_S, BP+BD,   64 };
        gemm_input<<<BP+BD+BS, 128>>>(P);
    }

    for (int l = 0; l < 2; l++) {
        init_buffers<<<cdiv(DSTN_TOT * CD, 256), 256>>>();

        // Phase A: all projections for this layer (one launch)
        {
            ParamsA P;
            JobA& j0 = P.job[0];
            j0.X = px; j0.M = N_P; j0.blk0 = 0; j0.nT = 5;
            j0.tl[0] = { Wq  + (size_t)(l*3+0)*4096, bq  + (size_t)(l*3+0)*64, pq };
            j0.tl[1] = { pWc + (size_t)(l*8+0)*4096, pbc + (size_t)(l*8+0)*64, pkr + kr0*64 };
            j0.tl[2] = { pWc + (size_t)(l*8+4)*4096, pbc + (size_t)(l*8+4)*64, pvr + kr0*64 };
            j0.tl[3] = { pWc + (size_t)(l*8+3)*4096, pbc + (size_t)(l*8+3)*64, pkr + kr3*64 };
            j0.tl[4] = { pWc + (size_t)(l*8+7)*4096, pbc + (size_t)(l*8+7)*64, pvr + kr3*64 };
            JobA& j1 = P.job[1];
            j1.X = px + (size_t)N_P*64; j1.M = N_D; j1.blk0 = BP; j1.nT = 5;
            j1.tl[0] = { Wq  + (size_t)(l*3+1)*4096, bq  + (size_t)(l*3+1)*64, pq + (size_t)N_P*64 };
            j1.tl[1] = { pWc + (size_t)(l*8+1)*4096, pbc + (size_t)(l*8+1)*64, pkr + kr1*64 };
            j1.tl[2] = { pWc + (size_t)(l*8+5)*4096, pbc + (size_t)(l*8+5)*64, pvr + kr1*64 };
            j1.tl[3] = { pWc + (size_t)(l*8+2)*4096, pbc + (size_t)(l*8+2)*64, pkr + kr2*64 };
            j1.tl[4] = { pWc + (size_t)(l*8+6)*4096, pbc + (size_t)(l*8+6)*64, pvr + kr2*64 };
            JobA& j2 = P.job[2];
            j2.X = px + (size_t)(N_P+N_D)*64; j2.M = N_S; j2.blk0 = BP+BD; j2.nT = 1;
            j2.tl[0] = { Wq + (size_t)(l*3+2)*4096, bq + (size_t)(l*3+2)*64, pq + (size_t)(N_P+N_D)*64 };
            j2.tl[1] = j2.tl[0]; j2.tl[2] = j2.tl[0]; j2.tl[3] = j2.tl[0]; j2.tl[4] = j2.tl[0];
            gemm_phaseA<<<BP+BD+BS, 128>>>(P);
        }

        // all relations, single launch
        edge_all<<<cdiv(ET * HD, 256), 256>>>(ei_pd, ei_dp, ei_ds, ei_ps);

        // epilogue: all 3 types (one launch)
        {
            float* Yb = (l == 0) ? px : out;
            ParamsE P;
            P.job[0] = { pnum + (size_t)N_D*64, pden + (size_t)N_D*4, nullptr, nullptr,
                         px, skip + l*3 + 0,
                         Wa + (size_t)(l*3+0)*4096, ba + (size_t)(l*3+0)*64, Yb,
                         N_P, 0 };
            P.job[1] = { pnum, pden, nullptr, nullptr,
                         px + (size_t)N_P*64, skip + l*3 + 1,
                         Wa + (size_t)(l*3+1)*4096, ba + (size_t)(l*3+1)*64, Yb + (size_t)N_P*64,
                         N_D, BP };
            P.job[2] = { pnum + (size_t)(N_D+N_P)*64, pden + (size_t)(N_D+N_P)*4,
                         pnum + (size_t)(N_D+N_P+N_S)*64, pden + (size_t)(N_D+N_P+N_S)*4,
                         px + (size_t)(N_P+N_D)*64, skip + l*3 + 2,
                         Wa + (size_t)(l*3+2)*4096, ba + (size_t)(l*3+2)*64, Yb + (size_t)(N_P+N_D)*64,
                         N_S, BP+BD };
            gemm_epilogue<<<BP+BD+BS, 128>>>(P);
        }
    }
    (void)in_sizes; (void)n_in; (void)out_size;
}

// round 4
// speedup vs baseline: 1.7870x; 1.0520x over previous
#include <cuda_runtime.h>
#include <math.h>

// ---------------- problem constants ----------------
#define N_P 100000
#define N_D 1000
#define N_S 5000
#define NT  (N_P + N_D + N_S)
#define CD  64
#define HD  4
#define E0 300000
#define E1 300000
#define E2 100000
#define E3 100000
#define ET (E0 + E1 + E2 + E3)
#define KREL_TOT (2*N_P + 2*N_D)
#define DSTN_TOT (N_D + N_P + 2*N_S)
#define XP 68   // Xs row pitch in floats (float4-aligned, conflict-free)

typedef unsigned long long u64;

// ---------------- device scratch ----------------
__device__ __align__(16) float g_x[NT * CD];
__device__ __align__(16) float g_q[NT * CD];
__device__ __align__(16) float g_krel[KREL_TOT * CD];
__device__ __align__(16) float g_vrel[KREL_TOT * CD];
__device__ __align__(16) float g_den[DSTN_TOT * HD];
__device__ __align__(16) float g_num[DSTN_TOT * CD];
__device__ __align__(16) float g_Wc[16 * CD * CD];
__device__ __align__(16) float g_bc[16 * CD];

// ---------------- f32x2 helpers ----------------
__device__ __forceinline__ u64 pack2(float x) {
    u64 r; asm("mov.b64 %0, {%1, %1};" : "=l"(r) : "f"(x)); return r;
}
__device__ __forceinline__ u64 fma2(u64 a, u64 b, u64 c) {
    u64 d; asm("fma.rn.f32x2 %0, %1, %2, %3;" : "=l"(d) : "l"(a), "l"(b), "l"(c)); return d;
}
__device__ __forceinline__ float2 unpack2(u64 a) {
    float2 f; asm("mov.b64 {%0, %1}, %2;" : "=f"(f.x), "=f"(f.y) : "l"(a)); return f;
}

// ---------------- shared inner loop: acc += Xs[128x64] @ Ws[64x64] ----------------
// Vectorized LDS: X as LDS.128 per 4-kk per row-slot, W as 2x LDS.128 per kk.
__device__ __forceinline__ void mma_core(const float* Xs, const float* Ws,
                                         int ty, int tx, u64 acc[8][4])
{
#pragma unroll 2
    for (int kk = 0; kk < 64; kk += 4) {
        float4 xv[8];
#pragma unroll
        for (int i = 0; i < 8; i++)
            xv[i] = *(const float4*)&Xs[(ty + i * 16) * XP + kk];
#pragma unroll
        for (int c = 0; c < 4; c++) {
            ulonglong2 wA = *(const ulonglong2*)&Ws[(kk + c) * 64 + tx * 8];
            ulonglong2 wB = *(const ulonglong2*)&Ws[(kk + c) * 64 + tx * 8 + 4];
            u64 w0 = wA.x, w1 = wA.y, w2 = wB.x, w3 = wB.y;
#pragma unroll
            for (int i = 0; i < 8; i++) {
                float xs = (c == 0) ? xv[i].x : (c == 1) ? xv[i].y
                         : (c == 2) ? xv[i].z : xv[i].w;
                u64 x2 = pack2(xs);
                acc[i][0] = fma2(x2, w0, acc[i][0]);
                acc[i][1] = fma2(x2, w1, acc[i][1]);
                acc[i][2] = fma2(x2, w2, acc[i][2]);
                acc[i][3] = fma2(x2, w3, acc[i][3]);
            }
        }
    }
}

// ---------------- combine weights:  Wc = W @ blockdiag(rel) * scale ----------------
__global__ void combine_weights(const float* __restrict__ Wk, const float* __restrict__ bk,
                                const float* __restrict__ Wv, const float* __restrict__ bv,
                                const float* __restrict__ a_rel, const float* __restrict__ m_rel,
                                const float* __restrict__ p_rel)
{
    int blk = blockIdx.x;
    int l  = blk >> 3;
    int kv = (blk >> 2) & 1;
    int r  = blk & 3;
    const int st_tab[4] = {0, 1, 1, 0};
    int st = st_tab[r];

    const float* Wbase = (kv == 0 ? Wk : Wv) + (size_t)(l*3 + st) * CD * CD;
    const float* bbase = (kv == 0 ? bk : bv) + (size_t)(l*3 + st) * CD;
    const float* rel   = (kv == 0 ? a_rel : m_rel) + (size_t)(l*4 + r) * HD * 16 * 16;

    __shared__ float srel[HD * 16 * 16];
    __shared__ float sscale[HD];
    int t = threadIdx.x; // 256
    for (int i = t; i < HD*256; i += 256) srel[i] = rel[i];
    if (t < HD) sscale[t] = (kv == 0) ? p_rel[(l*4 + r) * HD + t] * 0.25f : 1.0f;
    __syncthreads();

    float* Wc = g_Wc + (size_t)blk * CD * CD;
    float* bc = g_bc + (size_t)blk * CD;

    int c = t >> 2, h = t & 3;
    float wrow[16];
#pragma unroll
    for (int d = 0; d < 16; d++) wrow[d] = Wbase[c*CD + h*16 + d];
    float sc = sscale[h];
#pragma unroll
    for (int e = 0; e < 16; e++) {
        float s = 0.f;
#pragma unroll
        for (int d = 0; d < 16; d++) s += wrow[d] * srel[h*256 + d*16 + e];
        Wc[c*CD + h*16 + e] = s * sc;
    }
    if (t < CD) {
        int hh = t >> 4, ee = t & 15;
        float s = 0.f;
#pragma unroll
        for (int d = 0; d < 16; d++) s += bbase[hh*16 + d] * srel[hh*256 + d*16 + ee];
        bc[t] = s * sscale[hh];
    }
}

// ---------------- job descriptors ----------------
struct TileW { const float* W; const float* b; float* Y; };
struct JobA  { const float* X; int M; int blk0; int nT; TileW tl[5]; };
struct ParamsA { JobA job[3]; };

struct JobE {
    const float* num0; const float* den0;
    const float* num1; const float* den1;
    const float* xold; const float* skipp;
    const float* W; const float* b; float* Y;
    int M; int blk0;
};
struct ParamsE { JobE job[3]; };

struct JobI { const float* X; const float* W; const float* b; float* Y; int M; int blk0; int K; };
struct ParamsI { JobI job[3]; };

// ---------------- Phase A: multi-tile projection GEMM (K=64) ----------------
__global__ void __launch_bounds__(128)
gemm_phaseA(ParamsA P)
{
    __shared__ float Xs[128 * XP];
    __shared__ __align__(16) float Ws[64 * 64];
    int bx = blockIdx.x;
    int j = (bx >= P.job[2].blk0) ? 2 : (bx >= P.job[1].blk0) ? 1 : 0;
    const JobA& J = P.job[j];
    int m0 = (bx - J.blk0) * 128;
    int t = threadIdx.x;
    const int ty = t >> 3, tx = t & 7;

    // load X tile once
#pragma unroll
    for (int i = 0; i < 16; i++) {
        int f4 = t + i * 128;
        int row = f4 >> 4, c4 = f4 & 15;
        float4 v = make_float4(0.f, 0.f, 0.f, 0.f);
        if (m0 + row < J.M) v = *(const float4*)&J.X[(size_t)(m0 + row) * 64 + c4 * 4];
        *(float4*)&Xs[row * XP + c4 * 4] = v;
    }

    for (int ti = 0; ti < J.nT; ti++) {
        __syncthreads();
        const float* __restrict__ W = J.tl[ti].W;
#pragma unroll
        for (int i = 0; i < 8; i++) {
            int f4 = (t + i * 128) * 4;
            *(float4*)&Ws[f4] = *(const float4*)&W[f4];
        }
        __syncthreads();

        u64 acc[8][4];
#pragma unroll
        for (int i = 0; i < 8; i++)
#pragma unroll
            for (int k = 0; k < 4; k++) acc[i][k] = 0ull;

        mma_core(Xs, Ws, ty, tx, acc);

        const float* bias = J.tl[ti].b;
        float* Y = J.tl[ti].Y;
        float bb[8];
#pragma unroll
        for (int q = 0; q < 8; q++) bb[q] = bias[tx * 8 + q];
#pragma unroll
        for (int i = 0; i < 8; i++) {
            int row = m0 + ty + i * 16;
            if (row < J.M) {
                float o[8];
#pragma unroll
                for (int k = 0; k < 4; k++) {
                    float2 p = unpack2(acc[i][k]);
                    o[2*k] = p.x + bb[2*k]; o[2*k+1] = p.y + bb[2*k+1];
                }
                *(float4*)&Y[(size_t)row * 64 + tx * 8]     = make_float4(o[0], o[1], o[2], o[3]);
                *(float4*)&Y[(size_t)row * 64 + tx * 8 + 4] = make_float4(o[4], o[5], o[6], o[7]);
            }
        }
    }
}

// ---------------- Epilogue: gelu(softmax-out) @ Wa + skip gate ----------------
__global__ void __launch_bounds__(128)
gemm_epilogue(ParamsE P)
{
    __shared__ float Xs[128 * XP];
    __shared__ __align__(16) float Ws[64 * 64];
    int bx = blockIdx.x;
    int j = (bx >= P.job[2].blk0) ? 2 : (bx >= P.job[1].blk0) ? 1 : 0;
    const JobE& J = P.job[j];
    int m0 = (bx - J.blk0) * 128;
    int t = threadIdx.x;
    const int ty = t >> 3, tx = t & 7;

    // build gelu(num/den) tile (coalesced: lane-consecutive columns)
#pragma unroll
    for (int i = 0; i < 64; i++) {
        int idx = t + i * 128;
        int row = idx >> 6, cc = idx & 63;
        float val = 0.f;
        int n = m0 + row;
        if (n < J.M) {
            int h = cc >> 4;
            val = J.num0[(size_t)n * 64 + cc] / (J.den0[(size_t)n * 4 + h] + 1e-16f);
            if (J.num1)
                val += J.num1[(size_t)n * 64 + cc] / (J.den1[(size_t)n * 4 + h] + 1e-16f);
            val = 0.5f * val * (1.0f + erff(val * 0.70710678118654752f));
        }
        Xs[row * XP + cc] = val;
    }
#pragma unroll
    for (int i = 0; i < 8; i++) {
        int f4 = (t + i * 128) * 4;
        *(float4*)&Ws[f4] = *(const float4*)&J.W[f4];
    }
    __syncthreads();

    u64 acc[8][4];
#pragma unroll
    for (int i = 0; i < 8; i++)
#pragma unroll
        for (int k = 0; k < 4; k++) acc[i][k] = 0ull;

    mma_core(Xs, Ws, ty, tx, acc);

    float bb[8];
#pragma unroll
    for (int q = 0; q < 8; q++) bb[q] = J.b[tx * 8 + q];
    float s = 1.0f / (1.0f + expf(-J.skipp[0]));
    float om = 1.0f - s;

#pragma unroll
    for (int i = 0; i < 8; i++) {
        int row = m0 + ty + i * 16;
        if (row < J.M) {
            float o[8];
#pragma unroll
            for (int k = 0; k < 4; k++) {
                float2 p = unpack2(acc[i][k]);
                o[2*k] = p.x + bb[2*k]; o[2*k+1] = p.y + bb[2*k+1];
            }
            float4 x0 = *(const float4*)&J.xold[(size_t)row * 64 + tx * 8];
            float4 x1 = *(const float4*)&J.xold[(size_t)row * 64 + tx * 8 + 4];
            o[0] = s*o[0] + om*x0.x; o[1] = s*o[1] + om*x0.y;
            o[2] = s*o[2] + om*x0.z; o[3] = s*o[3] + om*x0.w;
            o[4] = s*o[4] + om*x1.x; o[5] = s*o[5] + om*x1.y;
            o[6] = s*o[6] + om*x1.z; o[7] = s*o[7] + om*x1.w;
            *(float4*)&J.Y[(size_t)row * 64 + tx * 8]     = make_float4(o[0], o[1], o[2], o[3]);
            *(float4*)&J.Y[(size_t)row * 64 + tx * 8 + 4] = make_float4(o[4], o[5], o[6], o[7]);
        }
    }
}

// ---------------- Input projections (runtime K: 64 or 128) ----------------
__global__ void __launch_bounds__(128)
gemm_input(ParamsI P)
{
    __shared__ float Xs[128 * XP];
    __shared__ __align__(16) float Ws[64 * 64];
    int bx = blockIdx.x;
    int j = (bx >= P.job[2].blk0) ? 2 : (bx >= P.job[1].blk0) ? 1 : 0;
    const JobI& J = P.job[j];
    int m0 = (bx - J.blk0) * 128;
    int t = threadIdx.x;
    const int ty = t >> 3, tx = t & 7;
    const int K = J.K;

    u64 acc[8][4];
#pragma unroll
    for (int i = 0; i < 8; i++)
#pragma unroll
        for (int k = 0; k < 4; k++) acc[i][k] = 0ull;

    for (int k0 = 0; k0 < K; k0 += 64) {
        __syncthreads();
#pragma unroll
        for (int i = 0; i < 16; i++) {
            int f4 = t + i * 128;
            int row = f4 >> 4, c4 = f4 & 15;
            float4 v = make_float4(0.f, 0.f, 0.f, 0.f);
            if (m0 + row < J.M) v = *(const float4*)&J.X[(size_t)(m0 + row) * K + k0 + c4 * 4];
            *(float4*)&Xs[row * XP + c4 * 4] = v;
        }
#pragma unroll
        for (int i = 0; i < 8; i++) {
            int f4 = (t + i * 128) * 4;
            *(float4*)&Ws[f4] = *(const float4*)&J.W[(size_t)k0 * 64 + f4];
        }
        __syncthreads();
        mma_core(Xs, Ws, ty, tx, acc);
    }

    float bb[8];
#pragma unroll
    for (int q = 0; q < 8; q++) bb[q] = J.b[tx * 8 + q];
#pragma unroll
    for (int i = 0; i < 8; i++) {
        int row = m0 + ty + i * 16;
        if (row < J.M) {
            float o[8];
#pragma unroll
            for (int k = 0; k < 4; k++) {
                float2 p = unpack2(acc[i][k]);
                o[2*k] = p.x + bb[2*k]; o[2*k+1] = p.y + bb[2*k+1];
            }
            *(float4*)&J.Y[(size_t)row * 64 + tx * 8]     = make_float4(o[0], o[1], o[2], o[3]);
            *(float4*)&J.Y[(size_t)row * 64 + tx * 8 + 4] = make_float4(o[4], o[5], o[6], o[7]);
        }
    }
}

// ---------------- merged single-pass edge kernel ----------------
// Softmax is shift-invariant; exp clamped at 60 to guard overflow (den >> eps).
__global__ void edge_all(const int* __restrict__ ei0, const int* __restrict__ ei1,
                         const int* __restrict__ ei2, const int* __restrict__ ei3)
{
    int gid = blockIdx.x * blockDim.x + threadIdx.x;
    if (gid >= ET * HD) return;
    int e = gid >> 2, h = gid & 3;

    const int* ei; int er, E, kvoff, qoff, dnoff;
    if (e < E0)                 { ei = ei0; er = e;            E = E0; kvoff = 0;           qoff = N_P;     dnoff = 0; }
    else if (e < E0+E1)         { ei = ei1; er = e - E0;       E = E1; kvoff = N_P;         qoff = 0;       dnoff = N_D; }
    else if (e < E0+E1+E2)      { ei = ei2; er = e - (E0+E1);  E = E2; kvoff = N_P+N_D;     qoff = N_P+N_D; dnoff = N_D+N_P; }
    else                        { ei = ei3; er = e-(E0+E1+E2); E = E3; kvoff = N_P+2*N_D;   qoff = N_P+N_D; dnoff = N_D+N_P+N_S; }

    int src = __ldg(&ei[er]);
    int dst = __ldg(&ei[E + er]);

    const float4* qp = (const float4*)&g_q[(size_t)(qoff + dst) * 64 + h * 16];
    const float4* kp = (const float4*)&g_krel[(size_t)(kvoff + src) * 64 + h * 16];
    float a = 0.f;
#pragma unroll
    for (int jj = 0; jj < 4; jj++) {
        float4 q4 = qp[jj], k4 = kp[jj];
        a += q4.x * k4.x + q4.y * k4.y + q4.z * k4.z + q4.w * k4.w;
    }
    float w = __expf(fminf(a, 60.f));
    atomicAdd(&g_den[(size_t)(dnoff + dst) * 4 + h], w);

    const float4* vp = (const float4*)&g_vrel[(size_t)(kvoff + src) * 64 + h * 16];
    float4* np = (float4*)&g_num[(size_t)(dnoff + dst) * 64 + h * 16];
#pragma unroll
    for (int jj = 0; jj < 4; jj++) {
        float4 v4 = vp[jj];
        atomicAdd(&np[jj], make_float4(v4.x * w, v4.y * w, v4.z * w, v4.w * w));
    }
}

// ---------------- buffer init ----------------
__global__ void init_buffers()
{
    int i = blockIdx.x * blockDim.x + threadIdx.x;
    if (i < DSTN_TOT * HD) g_den[i] = 0.f;
    if (i < DSTN_TOT * CD) g_num[i] = 0.f;
}

// ---------------- host orchestration ----------------
static inline int cdiv(int a, int b) { return (a + b - 1) / b; }

extern "C" void kernel_launch(void* const* d_in, const int* in_sizes, int n_in,
                              void* d_out, int out_size)
{
    const float* x_p   = (const float*)d_in[0];
    const float* x_d   = (const float*)d_in[1];
    const float* x_s   = (const float*)d_in[2];
    const float* Win_p = (const float*)d_in[3];
    const float* bin_p = (const float*)d_in[4];
    const float* Win_d = (const float*)d_in[5];
    const float* bin_d = (const float*)d_in[6];
    const float* Win_s = (const float*)d_in[7];
    const float* bin_s = (const float*)d_in[8];
    const float* Wk    = (const float*)d_in[9];
    const float* bk    = (const float*)d_in[10];
    const float* Wq    = (const float*)d_in[11];
    const float* bq    = (const float*)d_in[12];
    const float* Wv    = (const float*)d_in[13];
    const float* bv    = (const float*)d_in[14];
    const float* Wa    = (const float*)d_in[15];
    const float* ba    = (const float*)d_in[16];
    const float* a_rel = (const float*)d_in[17];
    const float* m_rel = (const float*)d_in[18];
    const float* p_rel = (const float*)d_in[19];
    const float* skip  = (const float*)d_in[20];
    const int*   ei_pd = (const int*)d_in[21];
    const int*   ei_dp = (const int*)d_in[22];
    const int*   ei_ds = (const int*)d_in[23];
    const int*   ei_ps = (const int*)d_in[24];
    float* out = (float*)d_out;

    float *px, *pq, *pkr, *pvr, *pnum, *pden, *pWc, *pbc;
    cudaGetSymbolAddress((void**)&px,   g_x);
    cudaGetSymbolAddress((void**)&pq,   g_q);
    cudaGetSymbolAddress((void**)&pkr,  g_krel);
    cudaGetSymbolAddress((void**)&pvr,  g_vrel);
    cudaGetSymbolAddress((void**)&pnum, g_num);
    cudaGetSymbolAddress((void**)&pden, g_den);
    cudaGetSymbolAddress((void**)&pWc,  g_Wc);
    cudaGetSymbolAddress((void**)&pbc,  g_bc);

    const int BP = cdiv(N_P, 128);
    const int BD = cdiv(N_D, 128);
    const int BS = cdiv(N_S, 128);
    const size_t kr0 = 0, kr1 = N_P, kr2 = N_P + N_D, kr3 = N_P + 2*N_D;

    combine_weights<<<16, 256>>>(Wk, bk, Wv, bv, a_rel, m_rel, p_rel);

    // input projections (one launch, 3 jobs)
    {
        ParamsI P;
        P.job[0] = { x_p, Win_p, bin_p, px,                        N_P, 0,       64 };
        P.job[1] = { x_d, Win_d, bin_d, px + (size_t)N_P*64,       N_D, BP,      128 };
        P.job[2] = { x_s, Win_s, bin_s, px + (size_t)(N_P+N_D)*64, N_S, BP+BD,   64 };
        gemm_input<<<BP+BD+BS, 128>>>(P);
    }

    for (int l = 0; l < 2; l++) {
        init_buffers<<<cdiv(DSTN_TOT * CD, 256), 256>>>();

        // Phase A: all projections for this layer (one launch)
        {
            ParamsA P;
            JobA& j0 = P.job[0];
            j0.X = px; j0.M = N_P; j0.blk0 = 0; j0.nT = 5;
            j0.tl[0] = { Wq  + (size_t)(l*3+0)*4096, bq  + (size_t)(l*3+0)*64, pq };
            j0.tl[1] = { pWc + (size_t)(l*8+0)*4096, pbc + (size_t)(l*8+0)*64, pkr + kr0*64 };
            j0.tl[2] = { pWc + (size_t)(l*8+4)*4096, pbc + (size_t)(l*8+4)*64, pvr + kr0*64 };
            j0.tl[3] = { pWc + (size_t)(l*8+3)*4096, pbc + (size_t)(l*8+3)*64, pkr + kr3*64 };
            j0.tl[4] = { pWc + (size_t)(l*8+7)*4096, pbc + (size_t)(l*8+7)*64, pvr + kr3*64 };
            JobA& j1 = P.job[1];
            j1.X = px + (size_t)N_P*64; j1.M = N_D; j1.blk0 = BP; j1.nT = 5;
            j1.tl[0] = { Wq  + (size_t)(l*3+1)*4096, bq  + (size_t)(l*3+1)*64, pq + (size_t)N_P*64 };
            j1.tl[1] = { pWc + (size_t)(l*8+1)*4096, pbc + (size_t)(l*8+1)*64, pkr + kr1*64 };
            j1.tl[2] = { pWc + (size_t)(l*8+5)*4096, pbc + (size_t)(l*8+5)*64, pvr + kr1*64 };
            j1.tl[3] = { pWc + (size_t)(l*8+2)*4096, pbc + (size_t)(l*8+2)*64, pkr + kr2*64 };
            j1.tl[4] = { pWc + (size_t)(l*8+6)*4096, pbc + (size_t)(l*8+6)*64, pvr + kr2*64 };
            JobA& j2 = P.job[2];
            j2.X = px + (size_t)(N_P+N_D)*64; j2.M = N_S; j2.blk0 = BP+BD; j2.nT = 1;
            j2.tl[0] = { Wq + (size_t)(l*3+2)*4096, bq + (size_t)(l*3+2)*64, pq + (size_t)(N_P+N_D)*64 };
            j2.tl[1] = j2.tl[0]; j2.tl[2] = j2.tl[0]; j2.tl[3] = j2.tl[0]; j2.tl[4] = j2.tl[0];
            gemm_phaseA<<<BP+BD+BS, 128>>>(P);
        }

        // all relations, single launch
        edge_all<<<cdiv(ET * HD, 256), 256>>>(ei_pd, ei_dp, ei_ds, ei_ps);

        // epilogue: all 3 types (one launch)
        {
            float* Yb = (l == 0) ? px : out;
            ParamsE P;
            P.job[0] = { pnum + (size_t)N_D*64, pden + (size_t)N_D*4, nullptr, nullptr,
                         px, skip + l*3 + 0,
                         Wa + (size_t)(l*3+0)*4096, ba + (size_t)(l*3+0)*64, Yb,
                         N_P, 0 };
            P.job[1] = { pnum, pden, nullptr, nullptr,
                         px + (size_t)N_P*64, skip + l*3 + 1,
                         Wa + (size_t)(l*3+1)*4096, ba + (size_t)(l*3+1)*64, Yb + (size_t)N_P*64,
                         N_D, BP };
            P.job[2] = { pnum + (size_t)(N_D+N_P)*64, pden + (size_t)(N_D+N_P)*4,
                         pnum + (size_t)(N_D+N_P+N_S)*64, pden + (size_t)(N_D+N_P+N_S)*4,
                         px + (size_t)(N_P+N_D)*64, skip + l*3 + 2,
                         Wa + (size_t)(l*3+2)*4096, ba + (size_t)(l*3+2)*64, Yb + (size_t)(N_P+N_D)*64,
                         N_S, BP+BD };
            gemm_epilogue<<<BP+BD+BS, 128>>>(P);
        }
    }
    (void)in_sizes; (void)n_in; (void)out_size;
}